// round 1
// baseline (speedup 1.0000x reference)
#include <cuda_runtime.h>
#include <math.h>

typedef unsigned long long ull;

// ---------------- problem dims ----------------
#define BT      4096        // 32*128 frames
#define KTOT    5376
#define NOUT    70          // 45+3+10+9+2+1
#define NPAD    80

// GEMM config
#define KSPLIT  7
#define KPB     (KTOT / KSPLIT)   // 768
#define KC      16
#define MT      32                // rows per block
#define NCHUNK  (KPB / KC)        // 48

// output layout: [J2d (32,128,21,2)][theta (32,128,48)][beta (32,128,10)]
#define J2D_OFF   0
#define THETA_OFF 172032
#define BETA_OFF  368640

// ---------------- scratch (static device globals; no allocation) ----------------
__device__ float g_part[(size_t)KSPLIT * BT * NPAD];   // ~9.2 MB partial GEMM
__device__ float g_params[(size_t)BT * NOUT];          // reduced params
__device__ float g_Jsh[480];                           // J_reg @ shapedirs  (16,3,10)
__device__ float g_Jt[48];                             // J_reg @ template   (16,3)

__device__ const int d_VIDX[5] = {743, 333, 443, 555, 678};
// J3d_re order: >=0 joint index, <0 -> mesh vertex (-1-based into d_VIDX)
__device__ const int d_MAP[21] = {0,13,14,15, -1, 1,2,3, -2, 4,5,6, -3, 10,11,12, -4, 7,8,9, -5};

// ---------------- helpers ----------------
__device__ __forceinline__ void ffma2(ull &d, ull a, ull b) {
    asm("fma.rn.f32x2 %0, %1, %2, %0;" : "+l"(d) : "l"(a), "l"(b));
}
__device__ __forceinline__ ull pack2(float w) {
    ull r; asm("mov.b64 %0, {%1, %1};" : "=l"(r) : "f"(w)); return r;
}
__device__ __forceinline__ void unpack2(ull v, float &lo, float &hi) {
    asm("mov.b64 {%0, %1}, %2;" : "=f"(lo), "=f"(hi) : "l"(v));
}

// ---------------- kernel 1: precompute J_reg@shapedirs, J_reg@template ----------------
__global__ void precompute_kernel(const float* __restrict__ Jreg,
                                  const float* __restrict__ shapedirs,
                                  const float* __restrict__ tmpl) {
    int gw   = blockIdx.x * (blockDim.x >> 5) + (threadIdx.x >> 5);
    int lane = threadIdx.x & 31;
    float s = 0.0f;
    if (gw < 480) {
        int j = gw / 30; int rem = gw % 30; int c = rem / 10; int k = rem % 10;
        for (int v = lane; v < 778; v += 32)
            s += Jreg[j * 778 + v] * shapedirs[v * 30 + c * 10 + k];
        #pragma unroll
        for (int o = 16; o; o >>= 1) s += __shfl_xor_sync(0xffffffffu, s, o);
        if (lane == 0) g_Jsh[gw] = s;
    } else if (gw < 528) {
        int t = gw - 480; int j = t / 3; int c = t % 3;
        for (int v = lane; v < 778; v += 32)
            s += Jreg[j * 778 + v] * tmpl[v * 3 + c];
        #pragma unroll
        for (int o = 16; o; o >>= 1) s += __shfl_xor_sync(0xffffffffu, s, o);
        if (lane == 0) g_Jt[t] = s;
    }
}

// ---------------- kernel 2: GEMM  params_part = x @ W^T (K-split) ----------------
// grid = 128 m-tiles * KSPLIT, 64 threads. Thread tile: 8 rows x 5 cols, f32x2 packed.
__global__ void __launch_bounds__(64) gemm_kernel(const float* __restrict__ x,
                                                  const float* __restrict__ W) {
    __shared__ __align__(16) float xs[KC * 34];   // [k][row], stride 34
    __shared__ __align__(16) float ws[KC * 81];   // [k][col], stride 81

    int bid = blockIdx.x;
    int mt = bid & 127;
    int ks = bid >> 7;
    int rbase = mt * MT;
    int kbase = ks * KPB;

    int t  = threadIdx.x;
    int tx = t & 15;        // col group: cols tx + 16*j
    int ty = t >> 4;        // row group: rows ty*8 .. ty*8+7

    ull acc[4][5];
    #pragma unroll
    for (int o = 0; o < 4; o++)
        #pragma unroll
        for (int j = 0; j < 5; j++) acc[o][j] = 0ull;

    int xrow = t >> 2;      // 0..15
    int xkq  = t & 3;       // float4 index within 16 k's

    for (int ch = 0; ch < NCHUNK; ch++) {
        int k0 = kbase + ch * KC;
        __syncthreads();
        // load x chunk (32 rows x 16 k), transpose into xs[k][row]
        #pragma unroll
        for (int pass = 0; pass < 2; pass++) {
            int r = xrow + pass * 16;
            const float4 v = *(const float4*)(x + (size_t)(rbase + r) * KTOT + k0 + xkq * 4);
            xs[(xkq * 4 + 0) * 34 + r] = v.x;
            xs[(xkq * 4 + 1) * 34 + r] = v.y;
            xs[(xkq * 4 + 2) * 34 + r] = v.z;
            xs[(xkq * 4 + 3) * 34 + r] = v.w;
        }
        // load W chunk (80 cols x 16 k), cols >= 70 zeroed
        for (int idx = t; idx < NPAD * KC; idx += 64) {
            int c  = idx >> 4;
            int kk = idx & 15;
            ws[kk * 81 + c] = (c < NOUT) ? W[(size_t)c * KTOT + k0 + kk] : 0.0f;
        }
        __syncthreads();

        #pragma unroll
        for (int kk = 0; kk < KC; kk++) {
            const float* xr = xs + kk * 34 + ty * 8;
            ull xv[4];
            #pragma unroll
            for (int o = 0; o < 4; o++)
                xv[o] = *(const ull*)(xr + 2 * o);
            ull wv[5];
            #pragma unroll
            for (int j = 0; j < 5; j++)
                wv[j] = pack2(ws[kk * 81 + tx + 16 * j]);
            #pragma unroll
            for (int o = 0; o < 4; o++)
                #pragma unroll
                for (int j = 0; j < 5; j++)
                    ffma2(acc[o][j], xv[o], wv[j]);
        }
    }

    float* dst = g_part + (size_t)ks * BT * NPAD;
    #pragma unroll
    for (int o = 0; o < 4; o++) {
        int r0 = rbase + ty * 8 + 2 * o;
        #pragma unroll
        for (int j = 0; j < 5; j++) {
            int c = tx + 16 * j;
            if (c < NOUT) {
                float lo, hi;
                unpack2(acc[o][j], lo, hi);
                dst[(size_t)r0 * NPAD + c]       = lo;
                dst[(size_t)(r0 + 1) * NPAD + c] = hi;
            }
        }
    }
}

// ---------------- kernel 3: reduce partials + bias, emit theta/beta ----------------
__global__ void reduce_kernel(const float* __restrict__ b, float* __restrict__ out) {
    int idx = blockIdx.x * blockDim.x + threadIdx.x;
    if (idx >= BT * NOUT) return;
    int row = idx / NOUT;
    int c   = idx - row * NOUT;
    float s = b[c];
    #pragma unroll
    for (int ks = 0; ks < KSPLIT; ks++)
        s += g_part[((size_t)ks * BT + row) * NPAD + c];
    g_params[idx] = s;
    if (c < 48)       out[THETA_OFF + row * 48 + c] = s;
    else if (c < 58)  out[BETA_OFF  + row * 10 + (c - 48)] = s;
}

// ---------------- kernel 4: decoder (1 warp per frame) ----------------
#define WSZ 728
__global__ void __launch_bounds__(256) decoder_kernel(
        const float* __restrict__ comps,      // (45,45)
        const float* __restrict__ meanh,      // (45)
        const float* __restrict__ tmpl,       // (778,3)
        const float* __restrict__ shapedirs,  // (778,3,10)
        const float* __restrict__ posedirs,   // (778,3,135)
        const float* __restrict__ lbs,        // (778,16)
        float* __restrict__ out) {
    __shared__ float sh[8 * WSZ];
    int wid  = threadIdx.x >> 5;
    int lane = threadIdx.x & 31;
    int bt   = blockIdx.x * 8 + wid;

    float* S  = sh + wid * WSZ;
    float* p  = S;          // 70
    float* hp = S + 70;     // 48
    float* R  = S + 118;    // 16*9
    float* Jj = S + 262;    // 16*3
    float* G  = S + 310;    // 16*12 (rows of [R|t])
    float* A  = S + 502;    // 16*12
    float* ch = S + 694;    // 5*3
    float* ms = S + 709;    // 5*3

    // 1. load params row
    for (int i = lane; i < NOUT; i += 32) p[i] = g_params[(size_t)bt * NOUT + i];
    __syncwarp();

    // 2. full pose: hp[0..2] = global rot; hp[3+i] = theta_pca @ comps + mean
    if (lane < 3) hp[lane] = p[lane];
    for (int i = lane; i < 45; i += 32) {
        float s = meanh[i];
        #pragma unroll 5
        for (int j = 0; j < 45; j++) s += p[3 + j] * comps[j * 45 + i];
        hp[3 + i] = s;
    }
    __syncwarp();

    // 3. rodrigues for 16 joints
    if (lane < 16) {
        int j = lane;
        float rx = hp[3*j], ry = hp[3*j+1], rz = hp[3*j+2];
        float th = sqrtf(rx*rx + ry*ry + rz*rz + 1e-8f);
        float inv = 1.0f / th;
        float nx = rx*inv, ny = ry*inv, nz = rz*inv;
        float cc = cosf(th), ssn = sinf(th), oc = 1.0f - cc;
        float* Rj = R + j * 9;
        Rj[0] = cc + oc*nx*nx;   Rj[1] = oc*nx*ny - ssn*nz; Rj[2] = oc*nx*nz + ssn*ny;
        Rj[3] = oc*nx*ny + ssn*nz; Rj[4] = cc + oc*ny*ny;   Rj[5] = oc*ny*nz - ssn*nx;
        Rj[6] = oc*nx*nz - ssn*ny; Rj[7] = oc*ny*nz + ssn*nx; Rj[8] = cc + oc*nz*nz;
    }
    // 4. joints J = Jsh @ beta + Jt  (48 outputs; lanes 0..31 then wrap)
    for (int idx = lane; idx < 48; idx += 32) {
        int j = idx / 3, c = idx - 3 * j;
        float s = g_Jt[idx];
        #pragma unroll
        for (int k = 0; k < 10; k++) s += g_Jsh[j * 30 + c * 10 + k] * p[48 + k];
        Jj[idx] = s;
    }
    __syncwarp();

    // 5. kinematic chain (5 fingers in parallel, depth 3)
    if (lane < 5) {
        float Gp[12];
        #pragma unroll
        for (int r = 0; r < 3; r++) {
            Gp[r*4+0] = R[r*3+0]; Gp[r*4+1] = R[r*3+1]; Gp[r*4+2] = R[r*3+2];
            Gp[r*4+3] = Jj[r];
        }
        if (lane == 0) {
            #pragma unroll
            for (int e = 0; e < 12; e++) G[e] = Gp[e];
        }
        int j = 3 * lane + 1;
        int parent = 0;
        #pragma unroll
        for (int s = 0; s < 3; s++, j++) {
            const float* Rc = R + j * 9;
            float d0 = Jj[j*3+0] - Jj[parent*3+0];
            float d1 = Jj[j*3+1] - Jj[parent*3+1];
            float d2 = Jj[j*3+2] - Jj[parent*3+2];
            float Gc[12];
            #pragma unroll
            for (int r = 0; r < 3; r++) {
                float a0 = Gp[r*4+0], a1 = Gp[r*4+1], a2 = Gp[r*4+2];
                Gc[r*4+0] = a0*Rc[0] + a1*Rc[3] + a2*Rc[6];
                Gc[r*4+1] = a0*Rc[1] + a1*Rc[4] + a2*Rc[7];
                Gc[r*4+2] = a0*Rc[2] + a1*Rc[5] + a2*Rc[8];
                Gc[r*4+3] = a0*d0 + a1*d1 + a2*d2 + Gp[r*4+3];
            }
            #pragma unroll
            for (int e = 0; e < 12; e++) { G[j*12+e] = Gc[e]; Gp[e] = Gc[e]; }
            parent = j;
        }
    }
    __syncwarp();

    // 6. A_j = [R_G | t_G - R_G * J_j]
    if (lane < 16) {
        int j = lane;
        #pragma unroll
        for (int r = 0; r < 3; r++) {
            float g0 = G[j*12+r*4+0], g1 = G[j*12+r*4+1], g2 = G[j*12+r*4+2];
            A[j*12+r*4+0] = g0; A[j*12+r*4+1] = g1; A[j*12+r*4+2] = g2;
            A[j*12+r*4+3] = G[j*12+r*4+3] - (g0*Jj[j*3+0] + g1*Jj[j*3+1] + g2*Jj[j*3+2]);
        }
    }
    __syncwarp();

    // 7. posed vertex positions at 5 mesh vertices (shapedirs + posedirs blend)
    if (lane < 15) {
        int v = lane / 3, c = lane - 3 * v;
        int vv = d_VIDX[v];
        float s = tmpl[vv * 3 + c];
        #pragma unroll
        for (int k = 0; k < 10; k++)
            s += shapedirs[vv * 30 + c * 10 + k] * p[48 + k];
        const float* pd = posedirs + (size_t)vv * 405 + c * 135;
        #pragma unroll 9
        for (int k = 0; k < 135; k++)
            s += pd[k] * R[9 + k];     // rod135[k] = R of joints 1..15 flattened
        ch[lane] = s;
    }
    __syncwarp();

    // 8. LBS: mesh = (sum_j w_j A_j) * [ch,1]
    if (lane < 15) {
        int v = lane / 3, r = lane - 3 * v;
        int vv = d_VIDX[v];
        float T0 = 0, T1 = 0, T2 = 0, T3 = 0;
        #pragma unroll
        for (int j = 0; j < 16; j++) {
            float w = lbs[vv * 16 + j];
            T0 += w * A[j*12+r*4+0];
            T1 += w * A[j*12+r*4+1];
            T2 += w * A[j*12+r*4+2];
            T3 += w * A[j*12+r*4+3];
        }
        ms[lane] = T0 * ch[v*3+0] + T1 * ch[v*3+1] + T2 * ch[v*3+2] + T3;
    }
    __syncwarp();

    // 9. reorder + camera projection:  J2d = c_s * (pt @ c_r3)[:2] + c_o
    if (lane < 21) {
        int m = d_MAP[lane];
        float q0, q1, q2;
        if (m >= 0) { q0 = G[m*12+3]; q1 = G[m*12+7]; q2 = G[m*12+11]; }
        else        { int mi = -m - 1; q0 = ms[mi*3+0]; q1 = ms[mi*3+1]; q2 = ms[mi*3+2]; }
        float cs = p[69];
        #pragma unroll
        for (int col = 0; col < 2; col++) {
            float u = q0 * p[58 + col] + q1 * p[61 + col] + q2 * p[64 + col];
            out[J2D_OFF + (size_t)bt * 42 + lane * 2 + col] = cs * u + p[67 + col];
        }
    }
}

// ---------------- launcher ----------------
extern "C" void kernel_launch(void* const* d_in, const int* in_sizes, int n_in,
                              void* d_out, int out_size) {
    const float* x         = (const float*)d_in[0];
    const float* W         = (const float*)d_in[1];
    const float* b         = (const float*)d_in[2];
    const float* comps     = (const float*)d_in[3];
    const float* meanh     = (const float*)d_in[4];
    const float* tmpl      = (const float*)d_in[5];
    const float* shapedirs = (const float*)d_in[6];
    const float* posedirs  = (const float*)d_in[7];
    const float* Jreg      = (const float*)d_in[8];
    const float* lbs       = (const float*)d_in[9];
    float* out = (float*)d_out;

    precompute_kernel<<<132, 128>>>(Jreg, shapedirs, tmpl);
    gemm_kernel<<<128 * KSPLIT, 64>>>(x, W);
    reduce_kernel<<<(BT * NOUT + 255) / 256, 256>>>(b, out);
    decoder_kernel<<<BT / 8, 256>>>(comps, meanh, tmpl, shapedirs, posedirs, lbs, out);
}

// round 2
// speedup vs baseline: 1.6913x; 1.6913x over previous
#include <cuda_runtime.h>
#include <math.h>

typedef unsigned long long ull;

// ---------------- problem dims ----------------
#define BT      4096        // 32*128 frames
#define KTOT    5376
#define NOUT    70          // 45+3+10+9+2+1
#define NPADP   72          // partial-buffer col stride

// GEMM config
#define KSPLIT  14
#define KPB     (KTOT / KSPLIT)   // 384
#define KC      16
#define NCH     (KPB / KC)        // 24
#define MT      128               // rows per block
#define GTHR    224               // 7 warps

// output layout: [J2d (32,128,21,2)][theta (32,128,48)][beta (32,128,10)]
#define J2D_OFF   0
#define THETA_OFF 172032
#define BETA_OFF  368640

// ---------------- scratch (static device globals; no allocation) ----------------
__device__ float g_part[(size_t)KSPLIT * BT * NPADP];  // ~16.5 MB partial GEMM
__device__ float g_params[(size_t)BT * NOUT];          // reduced params
__device__ float g_Jsh[480];                           // J_reg @ shapedirs  (16,3,10)
__device__ float g_Jt[48];                             // J_reg @ template   (16,3)
// gathered per-vertex constants for the 5 needed mesh vertices
__device__ __align__(16) float g_pd5[5][3][136];       // posedirs rows (pad->0)
__device__ float g_sd5[5][3][10];
__device__ float g_lbs5[5][16];
__device__ float g_tmpl5[16];

__device__ const int d_VIDX[5] = {743, 333, 443, 555, 678};
// J3d_re order: >=0 joint index, <0 -> mesh vertex (-1-based into d_VIDX)
__device__ const int d_MAP[21] = {0,13,14,15, -1, 1,2,3, -2, 4,5,6, -3, 10,11,12, -4, 7,8,9, -5};

// ---------------- helpers ----------------
__device__ __forceinline__ void ffma2(ull &d, ull a, ull b) {
    asm("fma.rn.f32x2 %0, %1, %2, %0;" : "+l"(d) : "l"(a), "l"(b));
}
__device__ __forceinline__ ull pack2(float w) {
    ull r; asm("mov.b64 %0, {%1, %1};" : "=l"(r) : "f"(w)); return r;
}
__device__ __forceinline__ void unpack2(ull v, float &lo, float &hi) {
    asm("mov.b64 {%0, %1}, %2;" : "=f"(lo), "=f"(hi) : "l"(v));
}
union U2 { ull u; float2 f; };

// ---------------- kernel 1: precompute ----------------
// blocks 0..131: J_reg@shapedirs / J_reg@template warp reductions
// blocks 132..139: gather vertex-5 constants
__global__ void precompute_kernel(const float* __restrict__ Jreg,
                                  const float* __restrict__ shapedirs,
                                  const float* __restrict__ tmpl,
                                  const float* __restrict__ posedirs,
                                  const float* __restrict__ lbs) {
    if (blockIdx.x < 132) {
        int gw   = blockIdx.x * (blockDim.x >> 5) + (threadIdx.x >> 5);
        int lane = threadIdx.x & 31;
        float s = 0.0f;
        if (gw < 480) {
            int j = gw / 30; int rem = gw % 30; int c = rem / 10; int k = rem % 10;
            for (int v = lane; v < 778; v += 32)
                s += Jreg[j * 778 + v] * shapedirs[v * 30 + c * 10 + k];
            #pragma unroll
            for (int o = 16; o; o >>= 1) s += __shfl_xor_sync(0xffffffffu, s, o);
            if (lane == 0) g_Jsh[gw] = s;
        } else if (gw < 528) {
            int t = gw - 480; int j = t / 3; int c = t % 3;
            for (int v = lane; v < 778; v += 32)
                s += Jreg[j * 778 + v] * tmpl[v * 3 + c];
            #pragma unroll
            for (int o = 16; o; o >>= 1) s += __shfl_xor_sync(0xffffffffu, s, o);
            if (lane == 0) g_Jt[t] = s;
        }
    } else {
        int tid = (blockIdx.x - 132) * blockDim.x + threadIdx.x;   // 0..1023
        float* pdf = &g_pd5[0][0][0];
        for (int i = tid; i < 5 * 3 * 136; i += 1024) {
            int v = i / 408; int rem = i % 408; int c = rem / 136; int k = rem % 136;
            pdf[i] = (k < 135) ? posedirs[(size_t)d_VIDX[v] * 405 + c * 135 + k] : 0.0f;
        }
        float* sdf = &g_sd5[0][0][0];
        for (int i = tid; i < 150; i += 1024) {
            int v = i / 30;
            sdf[i] = shapedirs[(size_t)d_VIDX[v] * 30 + (i % 30)];
        }
        float* lbf = &g_lbs5[0][0];
        for (int i = tid; i < 80; i += 1024)
            lbf[i] = lbs[(size_t)d_VIDX[i / 16] * 16 + (i % 16)];
        if (tid < 15) g_tmpl5[tid] = tmpl[(size_t)d_VIDX[tid / 3] * 3 + (tid % 3)];
    }
}

// ---------------- kernel 2: GEMM  params_part = x @ W^T (K-split) ----------------
// grid = 32 m-tiles * KSPLIT, 224 threads. Thread tile: 4 rows x 5 col-pairs (f32x2).
// Double-buffered smem with register staging; 1 syncthreads per 16-k chunk.
__global__ void __launch_bounds__(GTHR) gemm_kernel(const float* __restrict__ x,
                                                    const float* __restrict__ W) {
    __shared__ __align__(16) float xs[2][KC * 132];   // [k][row] transposed, stride 132
    __shared__ __align__(16) float ws[2][KC * 76];    // [k][col], stride 76

    int bid = blockIdx.x;
    int mt = bid & 31;
    int ks = bid >> 5;
    int rbase = mt * MT;
    int kbase = ks * KPB;

    int t  = threadIdx.x;
    int tx = t % 7;         // col-pair group: pairs tx + 7*j (j<5) -> cols 2p,2p+1
    int ty = t / 7;         // rows ty*4 .. ty*4+3

    // x-load geometry: 512 float4 per chunk; thread handles idx t, t+224, t+448(<512)
    int kq   = t & 3;             // float4 index within 16 k's (224%4==0 keeps it fixed)
    int row0 = t >> 2;            // rows row0, row0+56, row0+112
    bool has3 = (t < 64);

    // W-load geometry: 1120 floats = 5 per thread
    int wc[5], wk[5], wsidx[5];
    #pragma unroll
    for (int r = 0; r < 5; r++) {
        int idx = t + r * GTHR;
        wc[r] = idx >> 4; wk[r] = idx & 15;
        wsidx[r] = wk[r] * 76 + wc[r];
    }

    ull acc[4][5];
    #pragma unroll
    for (int o = 0; o < 4; o++)
        #pragma unroll
        for (int j = 0; j < 5; j++) acc[o][j] = 0ull;

    const float* xbase = x + (size_t)rbase * KTOT + kq * 4;
    float4 xr0, xr1, xr2; float wr[5];

    // ---- prefetch chunk 0 into registers ----
    {
        int k0 = kbase;
        const float* xb = xbase + k0;
        xr0 = *(const float4*)(xb + (size_t)row0 * KTOT);
        xr1 = *(const float4*)(xb + (size_t)(row0 + 56) * KTOT);
        if (has3) xr2 = *(const float4*)(xb + (size_t)(row0 + 112) * KTOT);
        #pragma unroll
        for (int r = 0; r < 5; r++) wr[r] = W[(size_t)wc[r] * KTOT + k0 + wk[r]];
    }

    for (int ch = 0; ch < NCH; ch++) {
        int cur = ch & 1;
        // ---- store staged registers into buf[cur] ----
        {
            float* xd = xs[cur];
            #pragma unroll
            for (int i = 0; i < 4; i++) {
                xd[(kq * 4 + i) * 132 + row0]        = ((float*)&xr0)[i];
                xd[(kq * 4 + i) * 132 + row0 + 56]   = ((float*)&xr1)[i];
            }
            if (has3) {
                #pragma unroll
                for (int i = 0; i < 4; i++)
                    xd[(kq * 4 + i) * 132 + row0 + 112] = ((float*)&xr2)[i];
            }
            float* wd = ws[cur];
            #pragma unroll
            for (int r = 0; r < 5; r++) wd[wsidx[r]] = wr[r];
        }
        // ---- prefetch next chunk ----
        if (ch + 1 < NCH) {
            int k0 = kbase + (ch + 1) * KC;
            const float* xb = xbase + k0;
            xr0 = *(const float4*)(xb + (size_t)row0 * KTOT);
            xr1 = *(const float4*)(xb + (size_t)(row0 + 56) * KTOT);
            if (has3) xr2 = *(const float4*)(xb + (size_t)(row0 + 112) * KTOT);
            #pragma unroll
            for (int r = 0; r < 5; r++) wr[r] = W[(size_t)wc[r] * KTOT + k0 + wk[r]];
        }
        __syncthreads();
        // ---- compute on buf[cur] ----
        const float* xc = xs[cur] + ty * 4;
        const float* wcp = ws[cur] + tx * 2;
        #pragma unroll
        for (int kk = 0; kk < KC; kk++) {
            float4 xq = *(const float4*)(xc + kk * 132);
            ull xa = pack2(xq.x), xb2 = pack2(xq.y), xc2 = pack2(xq.z), xd2 = pack2(xq.w);
            ull wv[5];
            #pragma unroll
            for (int j = 0; j < 5; j++)
                wv[j] = *(const ull*)(wcp + kk * 76 + 14 * j);
            #pragma unroll
            for (int j = 0; j < 5; j++) {
                ffma2(acc[0][j], xa,  wv[j]);
                ffma2(acc[1][j], xb2, wv[j]);
                ffma2(acc[2][j], xc2, wv[j]);
                ffma2(acc[3][j], xd2, wv[j]);
            }
        }
    }

    // ---- epilogue: write partials (float2 per pair) ----
    size_t base = ((size_t)ks * BT + rbase + ty * 4) * NPADP;
    #pragma unroll
    for (int o = 0; o < 4; o++) {
        #pragma unroll
        for (int j = 0; j < 5; j++) {
            U2 u; u.u = acc[o][j];
            *(float2*)(g_part + base + (size_t)o * NPADP + (tx + 7 * j) * 2) = u.f;
        }
    }
}

// ---------------- kernel 3: reduce partials + bias, emit theta/beta ----------------
__global__ void reduce_kernel(const float* __restrict__ b, float* __restrict__ out) {
    int idx = blockIdx.x * blockDim.x + threadIdx.x;
    if (idx >= BT * NOUT) return;
    int row = idx / NOUT;
    int c   = idx - row * NOUT;
    float s = b[c];
    #pragma unroll
    for (int ks = 0; ks < KSPLIT; ks++)
        s += g_part[((size_t)ks * BT + row) * NPADP + c];
    g_params[idx] = s;
    if (c < 48)       out[THETA_OFF + row * 48 + c] = s;
    else if (c < 58)  out[BETA_OFF  + row * 10 + (c - 48)] = s;
}

// ---------------- kernel 4: decoder (1 warp per frame) ----------------
#define WSZ     720
#define OFF_P   0     // 70 (pad 72)
#define OFF_HP  72    // 48
#define OFF_R   120   // 144 (16x9)
#define OFF_ROD 264   // 136 (16B aligned)
#define OFF_J   400   // 48
#define OFF_G   448   // 192
#define OFF_CT  640   // 48 corrected translations
#define OFF_CH  688   // 15
#define OFF_MS  704   // 15

__global__ void __launch_bounds__(256) decoder_kernel(
        const float* __restrict__ comps,      // (45,45)
        const float* __restrict__ meanh,      // (45)
        float* __restrict__ out) {
    __shared__ float cshare[2032];
    __shared__ __align__(16) float sh[8 * WSZ];
    for (int i = threadIdx.x; i < 2025; i += 256) cshare[i] = comps[i];
    __syncthreads();

    int wid  = threadIdx.x >> 5;
    int lane = threadIdx.x & 31;
    int bt   = blockIdx.x * 8 + wid;

    float* S   = sh + wid * WSZ;
    float* p   = S + OFF_P;
    float* hp  = S + OFF_HP;
    float* R   = S + OFF_R;
    float* rod = S + OFF_ROD;
    float* Jj  = S + OFF_J;
    float* G   = S + OFF_G;
    float* CT  = S + OFF_CT;
    float* ch  = S + OFF_CH;
    float* ms  = S + OFF_MS;

    // 1. load params row
    for (int i = lane; i < NOUT; i += 32) p[i] = g_params[(size_t)bt * NOUT + i];
    __syncwarp();

    // 2. full pose: hp[0..2] = global rot; hp[3+i] = theta_pca @ comps + mean
    if (lane < 3) hp[lane] = p[lane];
    for (int i = lane; i < 45; i += 32) {
        float s0 = meanh[i], s1 = 0.0f, s2 = 0.0f;
        #pragma unroll
        for (int j = 0; j < 45; j += 3) {
            s0 += p[3 + j]     * cshare[j * 45 + i];
            s1 += p[3 + j + 1] * cshare[(j + 1) * 45 + i];
            s2 += p[3 + j + 2] * cshare[(j + 2) * 45 + i];
        }
        hp[3 + i] = s0 + s1 + s2;
    }
    __syncwarp();

    // 3. rodrigues for 16 joints; joints 1..15 also mirrored into rod[135] (+pad 0)
    if (lane < 16) {
        int j = lane;
        float rx = hp[3*j], ry = hp[3*j+1], rz = hp[3*j+2];
        float th = sqrtf(rx*rx + ry*ry + rz*rz + 1e-8f);
        float inv = 1.0f / th;
        float nx = rx*inv, ny = ry*inv, nz = rz*inv;
        float cc = cosf(th), sn = sinf(th), oc = 1.0f - cc;
        float r0 = cc + oc*nx*nx,    r1 = oc*nx*ny - sn*nz, r2 = oc*nx*nz + sn*ny;
        float r3 = oc*nx*ny + sn*nz, r4 = cc + oc*ny*ny,    r5 = oc*ny*nz - sn*nx;
        float r6 = oc*nx*nz - sn*ny, r7 = oc*ny*nz + sn*nx, r8 = cc + oc*nz*nz;
        float* Rj = R + j * 9;
        Rj[0]=r0; Rj[1]=r1; Rj[2]=r2; Rj[3]=r3; Rj[4]=r4; Rj[5]=r5; Rj[6]=r6; Rj[7]=r7; Rj[8]=r8;
        if (j >= 1) {
            float* rd = rod + (j - 1) * 9;
            rd[0]=r0; rd[1]=r1; rd[2]=r2; rd[3]=r3; rd[4]=r4; rd[5]=r5; rd[6]=r6; rd[7]=r7; rd[8]=r8;
        } else {
            rod[135] = 0.0f;
        }
    }
    // 4. joints J = Jsh @ beta + Jt
    if (lane < 16) {
        int j = lane;
        #pragma unroll
        for (int c = 0; c < 3; c++) {
            float s = g_Jt[j * 3 + c];
            #pragma unroll
            for (int k = 0; k < 10; k++) s += g_Jsh[j * 30 + c * 10 + k] * p[48 + k];
            Jj[j * 3 + c] = s;
        }
    }
    __syncwarp();

    // 5. kinematic chain (5 fingers in parallel, depth 3)
    if (lane < 5) {
        float Gp[12];
        #pragma unroll
        for (int r = 0; r < 3; r++) {
            Gp[r*4+0] = R[r*3+0]; Gp[r*4+1] = R[r*3+1]; Gp[r*4+2] = R[r*3+2];
            Gp[r*4+3] = Jj[r];
        }
        if (lane == 0) {
            #pragma unroll
            for (int e = 0; e < 12; e++) G[e] = Gp[e];
        }
        int j = 3 * lane + 1;
        int parent = 0;
        #pragma unroll
        for (int s = 0; s < 3; s++, j++) {
            const float* Rc = R + j * 9;
            float d0 = Jj[j*3+0] - Jj[parent*3+0];
            float d1 = Jj[j*3+1] - Jj[parent*3+1];
            float d2 = Jj[j*3+2] - Jj[parent*3+2];
            float Gc[12];
            #pragma unroll
            for (int r = 0; r < 3; r++) {
                float a0 = Gp[r*4+0], a1 = Gp[r*4+1], a2 = Gp[r*4+2];
                Gc[r*4+0] = a0*Rc[0] + a1*Rc[3] + a2*Rc[6];
                Gc[r*4+1] = a0*Rc[1] + a1*Rc[4] + a2*Rc[7];
                Gc[r*4+2] = a0*Rc[2] + a1*Rc[5] + a2*Rc[8];
                Gc[r*4+3] = a0*d0 + a1*d1 + a2*d2 + Gp[r*4+3];
            }
            #pragma unroll
            for (int e = 0; e < 12; e++) { G[j*12+e] = Gc[e]; Gp[e] = Gc[e]; }
            parent = j;
        }
    }
    __syncwarp();

    // 6. corrected translations: CT[j] = t_G - R_G * J_j
    if (lane < 16) {
        int j = lane;
        #pragma unroll
        for (int r = 0; r < 3; r++) {
            float g0 = G[j*12+r*4+0], g1 = G[j*12+r*4+1], g2 = G[j*12+r*4+2];
            CT[j*3+r] = G[j*12+r*4+3] - (g0*Jj[j*3+0] + g1*Jj[j*3+1] + g2*Jj[j*3+2]);
        }
    }
    __syncwarp();

    // 7. posed positions at 5 mesh vertices: template + shape blend + pose blend
    if (lane < 15) {
        int v = lane / 3, c = lane - 3 * v;
        float s = g_tmpl5[lane];
        #pragma unroll
        for (int k = 0; k < 10; k++) s += g_sd5[v][c][k] * p[48 + k];
        ull a0 = 0ull, a1 = 0ull;
        const ull* pd = (const ull*)g_pd5[v][c];
        const ull* rr = (const ull*)rod;
        #pragma unroll
        for (int i = 0; i < 68; i += 2) {
            ffma2(a0, pd[i],     rr[i]);
            ffma2(a1, pd[i + 1], rr[i + 1]);
        }
        float l0, h0, l1, h1;
        unpack2(a0, l0, h0); unpack2(a1, l1, h1);
        ch[lane] = s + ((l0 + h0) + (l1 + h1));
    }
    __syncwarp();

    // 8. LBS: ms = (sum_j w_j [R_G|CT]) * [ch,1]
    if (lane < 15) {
        int v = lane / 3, r = lane - 3 * v;
        float T0 = 0, T1 = 0, T2 = 0, T3a = 0, T3b = 0;
        #pragma unroll
        for (int j = 0; j < 16; j++) {
            float w = g_lbs5[v][j];
            T0 += w * G[j*12+r*4+0];
            T1 += w * G[j*12+r*4+1];
            T2 += w * G[j*12+r*4+2];
            if (j & 1) T3a += w * CT[j*3+r]; else T3b += w * CT[j*3+r];
        }
        ms[lane] = T0 * ch[v*3+0] + T1 * ch[v*3+1] + T2 * ch[v*3+2] + (T3a + T3b);
    }
    __syncwarp();

    // 9. reorder + camera projection:  J2d = c_s * (pt @ c_r3)[:2] + c_o
    if (lane < 21) {
        int m = d_MAP[lane];
        float q0, q1, q2;
        if (m >= 0) { q0 = G[m*12+3]; q1 = G[m*12+7]; q2 = G[m*12+11]; }
        else        { int mi = -m - 1; q0 = ms[mi*3+0]; q1 = ms[mi*3+1]; q2 = ms[mi*3+2]; }
        float csv = p[69];
        #pragma unroll
        for (int col = 0; col < 2; col++) {
            float u = q0 * p[58 + col] + q1 * p[61 + col] + q2 * p[64 + col];
            out[J2D_OFF + (size_t)bt * 42 + lane * 2 + col] = csv * u + p[67 + col];
        }
    }
}

// ---------------- launcher ----------------
extern "C" void kernel_launch(void* const* d_in, const int* in_sizes, int n_in,
                              void* d_out, int out_size) {
    const float* x         = (const float*)d_in[0];
    const float* W         = (const float*)d_in[1];
    const float* b         = (const float*)d_in[2];
    const float* comps     = (const float*)d_in[3];
    const float* meanh     = (const float*)d_in[4];
    const float* tmpl      = (const float*)d_in[5];
    const float* shapedirs = (const float*)d_in[6];
    const float* posedirs  = (const float*)d_in[7];
    const float* Jreg      = (const float*)d_in[8];
    const float* lbs       = (const float*)d_in[9];
    float* out = (float*)d_out;

    precompute_kernel<<<140, 128>>>(Jreg, shapedirs, tmpl, posedirs, lbs);
    gemm_kernel<<<32 * KSPLIT, GTHR>>>(x, W);
    reduce_kernel<<<(BT * NOUT + 255) / 256, 256>>>(b, out);
    decoder_kernel<<<BT / 8, 256>>>(comps, meanh, out);
}

// round 4
// speedup vs baseline: 2.1958x; 1.2983x over previous
#include <cuda_runtime.h>
#include <cuda_bf16.h>
#include <math.h>
#include <stdint.h>

typedef unsigned long long ull;

// ---------------- problem dims ----------------
#define BT      4096
#define KTOT    5376
#define NOUT    70
#define NPADP   72

// GEMM config
#define KSPLIT   14
#define KPB      (KTOT / KSPLIT)     // 384
#define NCHUNKS  (KPB / 64)          // 6 chunks of K=64 per block
#define K16TOT   (KTOT / 16)         // 336
#define MTILES   32

// smem stage layout (bytes within one 51200B stage)
#define ST_AH   0
#define ST_AL   16384
#define ST_BH   32768
#define ST_BL   41984
#define STAGE_BYTES 51200
#define DYN_SMEM (2 * STAGE_BYTES)

// output layout
#define J2D_OFF   0
#define THETA_OFF 172032
#define BETA_OFF  368640

// ---------------- scratch ----------------
__device__ float g_part[(size_t)KSPLIT * BT * NPADP];   // 16.5 MB
__device__ __align__(16) uint2 g_Bh[K16TOT * 9 * 32];   // B frags hi (774KB)
__device__ __align__(16) uint2 g_Bl[K16TOT * 9 * 32];   // B frags lo
__device__ float g_Jsh[480];
__device__ float g_Jt[48];
__device__ __align__(16) float g_pd5[5][3][136];
__device__ float g_sd5[5][3][10];
__device__ float g_lbs5[5][16];
__device__ float g_tmpl5[16];

__device__ const int d_VIDX[5] = {743, 333, 443, 555, 678};
__device__ const int d_MAP[21] = {0,13,14,15, -1, 1,2,3, -2, 4,5,6, -3, 10,11,12, -4, 7,8,9, -5};

// ---------------- helpers ----------------
__device__ __forceinline__ uint32_t smem_u32(const void* p) {
    uint32_t a;
    asm("{ .reg .u64 t; cvta.to.shared.u64 t, %1; cvt.u32.u64 %0, t; }" : "=r"(a) : "l"(p));
    return a;
}
__device__ __forceinline__ void ffma2(ull &d, ull a, ull b) {
    asm("fma.rn.f32x2 %0, %1, %2, %0;" : "+l"(d) : "l"(a), "l"(b));
}
__device__ __forceinline__ void unpack2(ull v, float &lo, float &hi) {
    asm("mov.b64 {%0, %1}, %2;" : "=f"(lo), "=f"(hi) : "l"(v));
}
__device__ __forceinline__ uint32_t sw128(uint32_t off) { return off ^ ((off >> 3) & 0x70); }
__device__ __forceinline__ uint32_t pack_bf2(float a, float b) {
    __nv_bfloat162 h = __floats2bfloat162_rn(a, b);
    return *(uint32_t*)&h;
}
__device__ __forceinline__ void ldmatrix_x4(uint32_t* r, uint32_t addr) {
    asm volatile("ldmatrix.sync.aligned.m8n8.x4.shared.b16 {%0,%1,%2,%3}, [%4];"
                 : "=r"(r[0]), "=r"(r[1]), "=r"(r[2]), "=r"(r[3]) : "r"(addr));
}
__device__ __forceinline__ void mma16816(float* c, const uint32_t* a, uint32_t b0, uint32_t b1) {
    asm volatile("mma.sync.aligned.m16n8k16.row.col.f32.bf16.bf16.f32 "
                 "{%0,%1,%2,%3}, {%4,%5,%6,%7}, {%8,%9}, {%0,%1,%2,%3};"
                 : "+f"(c[0]), "+f"(c[1]), "+f"(c[2]), "+f"(c[3])
                 : "r"(a[0]), "r"(a[1]), "r"(a[2]), "r"(a[3]), "r"(b0), "r"(b1));
}

// ---------------- kernel 1: precompute ----------------
// blocks [0,132): J_reg reductions; [132,140): vertex gathers; [140,518): B frag tables
__global__ void precompute_kernel(const float* __restrict__ Jreg,
                                  const float* __restrict__ shapedirs,
                                  const float* __restrict__ tmpl,
                                  const float* __restrict__ posedirs,
                                  const float* __restrict__ lbs,
                                  const float* __restrict__ W) {
    if (blockIdx.x < 132) {
        int gw   = blockIdx.x * (blockDim.x >> 5) + (threadIdx.x >> 5);
        int lane = threadIdx.x & 31;
        float s = 0.0f;
        if (gw < 480) {
            int j = gw / 30; int rem = gw % 30; int c = rem / 10; int k = rem % 10;
            for (int v = lane; v < 778; v += 32)
                s += Jreg[j * 778 + v] * shapedirs[v * 30 + c * 10 + k];
            #pragma unroll
            for (int o = 16; o; o >>= 1) s += __shfl_xor_sync(0xffffffffu, s, o);
            if (lane == 0) g_Jsh[gw] = s;
        } else if (gw < 528) {
            int t = gw - 480; int j = t / 3; int c = t % 3;
            for (int v = lane; v < 778; v += 32)
                s += Jreg[j * 778 + v] * tmpl[v * 3 + c];
            #pragma unroll
            for (int o = 16; o; o >>= 1) s += __shfl_xor_sync(0xffffffffu, s, o);
            if (lane == 0) g_Jt[t] = s;
        }
    } else if (blockIdx.x < 140) {
        int tid = (blockIdx.x - 132) * blockDim.x + threadIdx.x;   // 0..1023
        float* pdf = &g_pd5[0][0][0];
        for (int i = tid; i < 5 * 3 * 136; i += 1024) {
            int v = i / 408; int rem = i % 408; int c = rem / 136; int k = rem % 136;
            pdf[i] = (k < 135) ? posedirs[(size_t)d_VIDX[v] * 405 + c * 135 + k] : 0.0f;
        }
        float* sdf = &g_sd5[0][0][0];
        for (int i = tid; i < 150; i += 1024) {
            int v = i / 30;
            sdf[i] = shapedirs[(size_t)d_VIDX[v] * 30 + (i % 30)];
        }
        float* lbf = &g_lbs5[0][0];
        for (int i = tid; i < 80; i += 1024)
            lbf[i] = lbs[(size_t)d_VIDX[i / 16] * 16 + (i % 16)];
        if (tid < 15) g_tmpl5[tid] = tmpl[(size_t)d_VIDX[tid / 3] * 3 + (tid % 3)];
    } else {
        // B fragment tables: idx = (kt*9 + j)*32 + lane, total 96768
        int base = (blockIdx.x - 140) * 128 + threadIdx.x;   // 0..48383
        #pragma unroll
        for (int e = 0; e < 2; e++) {
            int idx  = base + e * 48384;
            int lane = idx & 31;
            int grp  = idx >> 5;
            int j    = grp % 9;
            int kt   = grp / 9;
            int n    = j * 8 + (lane >> 2);
            int k0   = kt * 16 + 2 * (lane & 3);
            float b0 = 0, b1 = 0, b2 = 0, b3 = 0;
            if (n < NOUT) {
                const float* wp = W + (size_t)n * KTOT + k0;
                b0 = wp[0]; b1 = wp[1]; b2 = wp[8]; b3 = wp[9];
            }
            __nv_bfloat16 h0 = __float2bfloat16(b0), h1 = __float2bfloat16(b1);
            __nv_bfloat16 h2 = __float2bfloat16(b2), h3 = __float2bfloat16(b3);
            uint32_t hp0; { __nv_bfloat162 q; q.x = h0; q.y = h1; hp0 = *(uint32_t*)&q; }
            uint32_t hp1; { __nv_bfloat162 q; q.x = h2; q.y = h3; hp1 = *(uint32_t*)&q; }
            g_Bh[idx] = make_uint2(hp0, hp1);
            g_Bl[idx] = make_uint2(
                pack_bf2(b0 - __bfloat162float(h0), b1 - __bfloat162float(h1)),
                pack_bf2(b2 - __bfloat162float(h2), b3 - __bfloat162float(h3)));
        }
    }
}

// ---------------- kernel 2: HMMA GEMM (bf16 3-pass split, K-split 14) ----------------
__global__ void __launch_bounds__(256, 2) gemm_kernel(const float* __restrict__ x) {
    extern __shared__ __align__(1024) char dyn[];

    int t    = threadIdx.x;
    int wid  = t >> 5;
    int lane = t & 31;
    int mt   = blockIdx.x & 31;
    int ks   = blockIdx.x >> 5;
    int rbase = mt * 128;
    int kbase = ks * KPB;

    float acc[9][4];
    #pragma unroll
    for (int j = 0; j < 9; j++)
        #pragma unroll
        for (int i = 0; i < 4; i++) acc[j][i] = 0.0f;

    // x staging: thread -> (row, half); covers k in [half*32, half*32+32)
    int row  = t >> 1;
    int half = t & 1;
    const float* xrow = x + (size_t)(rbase + row) * KTOT + kbase + half * 32;

    float4 xr[8];
    #pragma unroll
    for (int i = 0; i < 8; i++) xr[i] = *(const float4*)(xrow + i * 4);

    uint32_t dynb = smem_u32(dyn);
    // ldmatrix geometry: row wbase + (lane&15), k seg (lane>>4)*8
    uint32_t arow_off = (uint32_t)((wid * 16 + (lane & 15)) * 128 + (lane >> 4) * 16);

    for (int ch = 0; ch < NCHUNKS; ch++) {
        int s = ch & 1;
        char* Ah = dyn + s * STAGE_BYTES + ST_AH;
        char* Al = dyn + s * STAGE_BYTES + ST_AL;
        // ---- store staged x as bf16 hi/lo (SW128) ----
        #pragma unroll
        for (int jq = 0; jq < 4; jq++) {
            float va[8];
            *(float4*)&va[0] = xr[2 * jq];
            *(float4*)&va[4] = xr[2 * jq + 1];
            uint32_t H[4], L[4];
            #pragma unroll
            for (int p2 = 0; p2 < 4; p2++) {
                float v0 = va[2 * p2], v1 = va[2 * p2 + 1];
                __nv_bfloat16 h0 = __float2bfloat16(v0), h1 = __float2bfloat16(v1);
                __nv_bfloat162 hq; hq.x = h0; hq.y = h1;
                H[p2] = *(uint32_t*)&hq;
                L[p2] = pack_bf2(v0 - __bfloat162float(h0), v1 - __bfloat162float(h1));
            }
            uint32_t off = sw128((uint32_t)(row * 128 + (half * 32 + 8 * jq) * 2));
            *(uint4*)(Ah + off) = make_uint4(H[0], H[1], H[2], H[3]);
            *(uint4*)(Al + off) = make_uint4(L[0], L[1], L[2], L[3]);
        }
        // ---- copy B frag tables for this chunk (4 k16 steps) ----
        {
            size_t cbase = (size_t)(ks * (NCHUNKS * 4) + ch * 4) * 288;  // uint2 elements
            const uint4* srcH = (const uint4*)(g_Bh + cbase);
            const uint4* srcL = (const uint4*)(g_Bl + cbase);
            uint4* dH = (uint4*)(dyn + s * STAGE_BYTES + ST_BH);
            uint4* dL = (uint4*)(dyn + s * STAGE_BYTES + ST_BL);
            #pragma unroll
            for (int i = 0; i < 3; i++) {
                int idx = t + i * 256;
                if (idx < 576) { dH[idx] = srcH[idx]; dL[idx] = srcL[idx]; }
            }
        }
        // ---- prefetch next chunk's x ----
        if (ch + 1 < NCHUNKS) {
            const float* xb = xrow + (ch + 1) * 64;
            #pragma unroll
            for (int i = 0; i < 8; i++) xr[i] = *(const float4*)(xb + i * 4);
        }
        __syncthreads();
        // ---- mma over 4 k16 steps ----
        uint32_t ahb = dynb + s * STAGE_BYTES + ST_AH;
        uint32_t alb = dynb + s * STAGE_BYTES + ST_AL;
        const char* bhb = dyn + s * STAGE_BYTES + ST_BH;
        const char* blb = dyn + s * STAGE_BYTES + ST_BL;
        #pragma unroll
        for (int s16 = 0; s16 < 4; s16++) {
            uint32_t off = arow_off + s16 * 32;
            uint32_t sw  = off ^ ((off >> 3) & 0x70);
            uint32_t ah[4], al[4];
            ldmatrix_x4(ah, ahb + sw);
            ldmatrix_x4(al, alb + sw);
            int bofs = ((s16 * 9) * 32 + lane) * 8;
            #pragma unroll
            for (int j = 0; j < 9; j++) {
                uint2 bh = *(const uint2*)(bhb + bofs + j * 256);
                uint2 bl = *(const uint2*)(blb + bofs + j * 256);
                mma16816(acc[j], ah, bh.x, bh.y);
                mma16816(acc[j], al, bh.x, bh.y);
                mma16816(acc[j], ah, bl.x, bl.y);
            }
        }
    }

    // ---- epilogue: write partials ----
    int r0 = rbase + wid * 16 + (lane >> 2);
    int c0 = 2 * (lane & 3);
    float* dst = g_part + ((size_t)ks * BT + r0) * NPADP + c0;
    #pragma unroll
    for (int j = 0; j < 9; j++) {
        *(float2*)(dst + 8 * j)                      = make_float2(acc[j][0], acc[j][1]);
        *(float2*)(dst + 8 * (size_t)NPADP + 8 * j)  = make_float2(acc[j][2], acc[j][3]);
    }
}

// ---------------- kernel 3: decoder (fused reduce; 1 warp per frame) ----------------
#define WSZ     720
#define OFF_P   0
#define OFF_HP  72
#define OFF_R   120
#define OFF_ROD 264
#define OFF_J   400
#define OFF_G   448
#define OFF_CT  640
#define OFF_CH  688
#define OFF_MS  704

__global__ void __launch_bounds__(256) decoder_kernel(
        const float* __restrict__ comps,
        const float* __restrict__ meanh,
        const float* __restrict__ bias,
        float* __restrict__ out) {
    __shared__ float cshare[2032];
    __shared__ __align__(16) float pdsh[2040];           // g_pd5 copy
    __shared__ __align__(16) float sh[8 * WSZ];
    for (int i = threadIdx.x; i < 2025; i += 256) cshare[i] = comps[i];
    for (int i = threadIdx.x; i < 2040; i += 256) pdsh[i] = (&g_pd5[0][0][0])[i];
    __syncthreads();

    int wid  = threadIdx.x >> 5;
    int lane = threadIdx.x & 31;
    int bt   = blockIdx.x * 8 + wid;

    float* S   = sh + wid * WSZ;
    float* p   = S + OFF_P;
    float* hp  = S + OFF_HP;
    float* R   = S + OFF_R;
    float* rod = S + OFF_ROD;
    float* Jj  = S + OFF_J;
    float* G   = S + OFF_G;
    float* CT  = S + OFF_CT;
    float* ch  = S + OFF_CH;
    float* ms  = S + OFF_MS;

    // 1. fused reduce: p = bias + sum partials; emit theta/beta
    for (int i = lane; i < NOUT; i += 32) {
        float s = bias[i];
        const float* gp = g_part + (size_t)bt * NPADP + i;
        #pragma unroll
        for (int ksi = 0; ksi < KSPLIT; ksi++)
            s += gp[(size_t)ksi * BT * NPADP];
        p[i] = s;
        if (i < 48)      out[THETA_OFF + bt * 48 + i] = s;
        else if (i < 58) out[BETA_OFF + bt * 10 + (i - 48)] = s;
    }
    __syncwarp();

    // 2. full pose
    if (lane < 3) hp[lane] = p[lane];
    for (int i = lane; i < 45; i += 32) {
        float s0 = meanh[i], s1 = 0.0f, s2 = 0.0f;
        #pragma unroll
        for (int j = 0; j < 45; j += 3) {
            s0 += p[3 + j]     * cshare[j * 45 + i];
            s1 += p[3 + j + 1] * cshare[(j + 1) * 45 + i];
            s2 += p[3 + j + 2] * cshare[(j + 2) * 45 + i];
        }
        hp[3 + i] = s0 + s1 + s2;
    }
    __syncwarp();

    // 3. rodrigues
    if (lane < 16) {
        int j = lane;
        float rx = hp[3*j], ry = hp[3*j+1], rz = hp[3*j+2];
        float th = sqrtf(rx*rx + ry*ry + rz*rz + 1e-8f);
        float inv = 1.0f / th;
        float nx = rx*inv, ny = ry*inv, nz = rz*inv;
        float sn, cc;
        __sincosf(th, &sn, &cc);
        float oc = 1.0f - cc;
        float r0 = cc + oc*nx*nx,    r1 = oc*nx*ny - sn*nz, r2 = oc*nx*nz + sn*ny;
        float r3 = oc*nx*ny + sn*nz, r4 = cc + oc*ny*ny,    r5 = oc*ny*nz - sn*nx;
        float r6 = oc*nx*nz - sn*ny, r7 = oc*ny*nz + sn*nx, r8 = cc + oc*nz*nz;
        float* Rj = R + j * 9;
        Rj[0]=r0; Rj[1]=r1; Rj[2]=r2; Rj[3]=r3; Rj[4]=r4; Rj[5]=r5; Rj[6]=r6; Rj[7]=r7; Rj[8]=r8;
        if (j >= 1) {
            float* rd = rod + (j - 1) * 9;
            rd[0]=r0; rd[1]=r1; rd[2]=r2; rd[3]=r3; rd[4]=r4; rd[5]=r5; rd[6]=r6; rd[7]=r7; rd[8]=r8;
        } else {
            rod[135] = 0.0f;
        }
    }
    // 4. joints
    if (lane < 16) {
        int j = lane;
        #pragma unroll
        for (int c = 0; c < 3; c++) {
            float s = g_Jt[j * 3 + c];
            #pragma unroll
            for (int k = 0; k < 10; k++) s += g_Jsh[j * 30 + c * 10 + k] * p[48 + k];
            Jj[j * 3 + c] = s;
        }
    }
    __syncwarp();

    // 5. kinematic chain
    if (lane < 5) {
        float Gp[12];
        #pragma unroll
        for (int r = 0; r < 3; r++) {
            Gp[r*4+0] = R[r*3+0]; Gp[r*4+1] = R[r*3+1]; Gp[r*4+2] = R[r*3+2];
            Gp[r*4+3] = Jj[r];
        }
        if (lane == 0) {
            #pragma unroll
            for (int e = 0; e < 12; e++) G[e] = Gp[e];
        }
        int j = 3 * lane + 1;
        int parent = 0;
        #pragma unroll
        for (int s = 0; s < 3; s++, j++) {
            const float* Rc = R + j * 9;
            float d0 = Jj[j*3+0] - Jj[parent*3+0];
            float d1 = Jj[j*3+1] - Jj[parent*3+1];
            float d2 = Jj[j*3+2] - Jj[parent*3+2];
            float Gc[12];
            #pragma unroll
            for (int r = 0; r < 3; r++) {
                float a0 = Gp[r*4+0], a1 = Gp[r*4+1], a2 = Gp[r*4+2];
                Gc[r*4+0] = a0*Rc[0] + a1*Rc[3] + a2*Rc[6];
                Gc[r*4+1] = a0*Rc[1] + a1*Rc[4] + a2*Rc[7];
                Gc[r*4+2] = a0*Rc[2] + a1*Rc[5] + a2*Rc[8];
                Gc[r*4+3] = a0*d0 + a1*d1 + a2*d2 + Gp[r*4+3];
            }
            #pragma unroll
            for (int e = 0; e < 12; e++) { G[j*12+e] = Gc[e]; Gp[e] = Gc[e]; }
            parent = j;
        }
    }
    __syncwarp();

    // 6. corrected translations
    if (lane < 16) {
        int j = lane;
        #pragma unroll
        for (int r = 0; r < 3; r++) {
            float g0 = G[j*12+r*4+0], g1 = G[j*12+r*4+1], g2 = G[j*12+r*4+2];
            CT[j*3+r] = G[j*12+r*4+3] - (g0*Jj[j*3+0] + g1*Jj[j*3+1] + g2*Jj[j*3+2]);
        }
    }
    __syncwarp();

    // 7. pose-blend dot over 30 lanes (135 terms split in half), then shuffle
    float contrib = 0.0f;
    {
        int o = (lane < 15) ? lane : lane - 15;
        int halfk = (lane < 15) ? 0 : 1;
        if (lane < 30) {
            int v = o / 3, c = o - 3 * v;
            const ull* pd = (const ull*)&pdsh[(v * 3 + c) * 136] + halfk * 34;
            const ull* rr = (const ull*)rod + halfk * 34;
            ull a0 = 0ull, a1 = 0ull;
            #pragma unroll
            for (int i = 0; i < 34; i += 2) {
                ffma2(a0, pd[i],     rr[i]);
                ffma2(a1, pd[i + 1], rr[i + 1]);
            }
            float l0, h0, l1, h1;
            unpack2(a0, l0, h0); unpack2(a1, l1, h1);
            contrib = (l0 + h0) + (l1 + h1);
        }
    }
    float other = __shfl_down_sync(0xffffffffu, contrib, 15);
    if (lane < 15) {
        int v = lane / 3, c = lane - 3 * v;
        float s = g_tmpl5[lane];
        #pragma unroll
        for (int k = 0; k < 10; k++) s += g_sd5[v][c][k] * p[48 + k];
        ch[lane] = s + contrib + other;
    }
    __syncwarp();

    // 8. LBS at 5 vertices
    if (lane < 15) {
        int v = lane / 3, r = lane - 3 * v;
        float T0 = 0, T1 = 0, T2 = 0, T3a = 0, T3b = 0;
        #pragma unroll
        for (int j = 0; j < 16; j++) {
            float w = g_lbs5[v][j];
            T0 += w * G[j*12+r*4+0];
            T1 += w * G[j*12+r*4+1];
            T2 += w * G[j*12+r*4+2];
            if (j & 1) T3a += w * CT[j*3+r]; else T3b += w * CT[j*3+r];
        }
        ms[lane] = T0 * ch[v*3+0] + T1 * ch[v*3+1] + T2 * ch[v*3+2] + (T3a + T3b);
    }
    __syncwarp();

    // 9. reorder + projection
    if (lane < 21) {
        int m = d_MAP[lane];
        float q0, q1, q2;
        if (m >= 0) { q0 = G[m*12+3]; q1 = G[m*12+7]; q2 = G[m*12+11]; }
        else        { int mi = -m - 1; q0 = ms[mi*3+0]; q1 = ms[mi*3+1]; q2 = ms[mi*3+2]; }
        float csv = p[69];
        #pragma unroll
        for (int col = 0; col < 2; col++) {
            float u = q0 * p[58 + col] + q1 * p[61 + col] + q2 * p[64 + col];
            out[J2D_OFF + (size_t)bt * 42 + lane * 2 + col] = csv * u + p[67 + col];
        }
    }
}

// ---------------- launcher ----------------
extern "C" void kernel_launch(void* const* d_in, const int* in_sizes, int n_in,
                              void* d_out, int out_size) {
    const float* x         = (const float*)d_in[0];
    const float* W         = (const float*)d_in[1];
    const float* b         = (const float*)d_in[2];
    const float* comps     = (const float*)d_in[3];
    const float* meanh     = (const float*)d_in[4];
    const float* tmpl      = (const float*)d_in[5];
    const float* shapedirs = (const float*)d_in[6];
    const float* posedirs  = (const float*)d_in[7];
    const float* Jreg      = (const float*)d_in[8];
    const float* lbs       = (const float*)d_in[9];
    float* out = (float*)d_out;

    cudaFuncSetAttribute(gemm_kernel, cudaFuncAttributeMaxDynamicSharedMemorySize, DYN_SMEM);

    precompute_kernel<<<518, 128>>>(Jreg, shapedirs, tmpl, posedirs, lbs, W);
    gemm_kernel<<<MTILES * KSPLIT, 256, DYN_SMEM>>>(x);
    decoder_kernel<<<BT / 8, 256>>>(comps, meanh, b, out);
}